// round 10
// baseline (speedup 1.0000x reference)
#include <cuda_runtime.h>

// TwoRobots Euler step, affine form. R10: R8's winning cache policy
// (pin x+w with evict_last, stream u+out with evict_first) + unroll x2:
// each thread handles items i and i+256 (block tile = 512 items), giving
// 10 front-batched loads per thread to cover warm L2-hit latency, and
// halving the grid (fewer waves).

#define HSTEP 0.05f
#define KS    2.0f
#define CD    2.0f

__device__ __forceinline__ unsigned long long mkpolicy_pin() {
    unsigned long long p;
    asm("createpolicy.fractional.L2::evict_last.b64 %0, 1.0;" : "=l"(p));
    return p;
}

__device__ __forceinline__ unsigned long long mkpolicy_stream() {
    unsigned long long p;
    asm("createpolicy.fractional.L2::evict_first.b64 %0, 1.0;" : "=l"(p));
    return p;
}

__device__ __forceinline__ float4 ldg_hint(const float4* p, unsigned long long pol) {
    float4 v;
    asm volatile("ld.global.L2::cache_hint.v4.f32 {%0,%1,%2,%3}, [%4], %5;"
                 : "=f"(v.x), "=f"(v.y), "=f"(v.z), "=f"(v.w)
                 : "l"(p), "l"(pol));
    return v;
}

__device__ __forceinline__ void stg_hint(float4* p, float4 v, unsigned long long pol) {
    asm volatile("st.global.L2::cache_hint.v4.f32 [%0], {%1,%2,%3,%4}, %5;"
                 :: "l"(p), "f"(v.x), "f"(v.y), "f"(v.z), "f"(v.w), "l"(pol)
                 : "memory");
}

__global__ __launch_bounds__(256)
void tworobots_pair_u2(const float4* __restrict__ x,
                       const float4* __restrict__ u,
                       const float4* __restrict__ w,
                       const float*  __restrict__ xbar,
                       float4* __restrict__ out,
                       int n4)
{
    // Block tile covers 512 items: thread t handles i0 = base+t and i1 = i0+256.
    const int i0 = blockIdx.x * 512 + threadIdx.x;
    const int i1 = i0 + 256;

    const int pair = blockIdx.y;                 // 0..3
    const int pr   = pair + ((pair >> 1) << 1);  // 0,1,4,5
    const int vr   = pr + 2;                     // 2,3,6,7

    const float xb = __ldg(&xbar[pr]);

    const unsigned long long polPin    = mkpolicy_pin();
    const unsigned long long polStream = mkpolicy_stream();

    const float4* xpP = x + (size_t)pr   * n4;
    const float4* xvP = x + (size_t)vr   * n4;
    const float4* uP  = u + (size_t)pair * n4;
    const float4* wpP = w + (size_t)pr   * n4;
    const float4* wvP = w + (size_t)vr   * n4;
    float4* opP = out + (size_t)pr * n4;
    float4* ovP = out + (size_t)vr * n4;

    const bool ok0 = (i0 < n4);
    const bool ok1 = (i1 < n4);

    float4 xpA, xvA, uuA, wpA, wvA;
    float4 xpB, xvB, uuB, wpB, wvB;

    // Front-batch up to 10 independent loads.
    if (ok0) {
        xpA = ldg_hint(xpP + i0, polPin);
        xvA = ldg_hint(xvP + i0, polPin);
        uuA = ldg_hint(uP  + i0, polStream);
        wpA = ldg_hint(wpP + i0, polPin);
        wvA = ldg_hint(wvP + i0, polPin);
    }
    if (ok1) {
        xpB = ldg_hint(xpP + i1, polPin);
        xvB = ldg_hint(xvP + i1, polPin);
        uuB = ldg_hint(uP  + i1, polStream);
        wpB = ldg_hint(wpP + i1, polPin);
        wvB = ldg_hint(wvP + i1, polPin);
    }

#define LANE(c, xp, xv, uu, wp, wv, op, ov)                      \
    {                                                            \
        float fg = fmaf(-KS, (xp.c - xb), -CD * xv.c);           \
        op.c = fmaf(HSTEP, xv.c, xp.c) + wp.c;                   \
        ov.c = fmaf(HSTEP, (fg + uu.c), xv.c) + wv.c;            \
    }

    if (ok0) {
        float4 op, ov;
        LANE(x, xpA, xvA, uuA, wpA, wvA, op, ov)
        LANE(y, xpA, xvA, uuA, wpA, wvA, op, ov)
        LANE(z, xpA, xvA, uuA, wpA, wvA, op, ov)
        LANE(w, xpA, xvA, uuA, wpA, wvA, op, ov)
        stg_hint(opP + i0, op, polStream);
        stg_hint(ovP + i0, ov, polStream);
    }
    if (ok1) {
        float4 op, ov;
        LANE(x, xpB, xvB, uuB, wpB, wvB, op, ov)
        LANE(y, xpB, xvB, uuB, wpB, wvB, op, ov)
        LANE(z, xpB, xvB, uuB, wpB, wvB, op, ov)
        LANE(w, xpB, xvB, uuB, wpB, wvB, op, ov)
        stg_hint(opP + i1, op, polStream);
        stg_hint(ovP + i1, ov, polStream);
    }
#undef LANE
}

// Scalar fallback (B % 4 != 0) — plain accesses, same math.
__global__ __launch_bounds__(256)
void tworobots_pair_scalar(const float* __restrict__ x,
                           const float* __restrict__ u,
                           const float* __restrict__ w,
                           const float* __restrict__ xbar,
                           float* __restrict__ out,
                           int B)
{
    const int i = blockIdx.x * blockDim.x + threadIdx.x;
    if (i >= B) return;

    const int pair = blockIdx.y;
    const int pr   = pair + ((pair >> 1) << 1);
    const int vr   = pr + 2;

    const float xb = __ldg(&xbar[pr]);

    const float xp = x[(size_t)pr   * B + i];
    const float xv = x[(size_t)vr   * B + i];
    const float uu = u[(size_t)pair * B + i];
    const float wp = w[(size_t)pr   * B + i];
    const float wv = w[(size_t)vr   * B + i];

    float fg = fmaf(-KS, (xp - xb), -CD * xv);
    out[(size_t)pr * B + i] = fmaf(HSTEP, xv, xp) + wp;
    out[(size_t)vr * B + i] = fmaf(HSTEP, (fg + uu), xv) + wv;
}

extern "C" void kernel_launch(void* const* d_in, const int* in_sizes, int n_in,
                              void* d_out, int out_size)
{
    const float* x    = (const float*)d_in[0];   // [8, B]
    const float* u    = (const float*)d_in[1];   // [4, B]
    const float* w    = (const float*)d_in[2];   // [8, B]
    const float* xbar = (const float*)d_in[3];   // [8]
    float* out = (float*)d_out;                  // [8, B]

    const int B = in_sizes[0] / 8;
    const int threads = 256;

    if ((B & 3) == 0) {
        const int n4 = B / 4;
        dim3 grid((n4 + 511) / 512, 4);
        tworobots_pair_u2<<<grid, threads>>>((const float4*)x, (const float4*)u,
                                             (const float4*)w, xbar,
                                             (float4*)out, n4);
    } else {
        dim3 grid((B + threads - 1) / threads, 4);
        tworobots_pair_scalar<<<grid, threads>>>(x, u, w, xbar, out, B);
    }
}